// round 13
// baseline (speedup 1.0000x reference)
#include <cuda_runtime.h>
#include <cuda_fp16.h>
#include <cstdint>
#include <cstddef>

// y[8192,4096] = x @ sign(W)^T + bias. fp16 mma.sync GEMM, 256x128x64 tiles,
// 512 threads, 3-stage cp.async pipeline.
#define DIM_M 8192
#define DIM_N 4096
#define DIM_K 4096
#define BM 256
#define BN 128
#define BK 64
#define NCH (DIM_K / BK)            // 64
#define A_BYTES (BM * 128)          // 32768
#define B_BYTES (BN * 128)          // 16384
#define STG_BYTES (A_BYTES + B_BYTES)       // 49152
#define SMEM_TOTAL (3 * STG_BYTES)          // 147456

__device__ __half g_xh[(size_t)DIM_M * DIM_K];   // 64 MB
__device__ __half g_wb[(size_t)DIM_N * DIM_K];   // 32 MB

__device__ __forceinline__ uint32_t smem_u32(const void* p) {
    uint32_t a;
    asm("{ .reg .u64 t; cvta.to.shared.u64 t, %1; cvt.u32.u64 %0, t; }" : "=r"(a) : "l"(p));
    return a;
}
__device__ __forceinline__ uint32_t swz(uint32_t off) { return off ^ ((off >> 3) & 0x70); }
__device__ __forceinline__ void cp16(uint32_t dst, const void* src) {
    asm volatile("cp.async.cg.shared.global [%0], [%1], 16;" :: "r"(dst), "l"(src));
}
__device__ __forceinline__ void ldm4(uint32_t* r, uint32_t addr) {
    asm volatile("ldmatrix.sync.aligned.m8n8.x4.shared.b16 {%0,%1,%2,%3}, [%4];"
                 : "=r"(r[0]), "=r"(r[1]), "=r"(r[2]), "=r"(r[3]) : "r"(addr));
}
__device__ __forceinline__ void mma16816(float* d, const uint32_t* a,
                                         uint32_t b0, uint32_t b1) {
    asm volatile(
        "mma.sync.aligned.m16n8k16.row.col.f32.f16.f16.f32 "
        "{%0,%1,%2,%3}, {%4,%5,%6,%7}, {%8,%9}, {%0,%1,%2,%3};"
        : "+f"(d[0]), "+f"(d[1]), "+f"(d[2]), "+f"(d[3])
        : "r"(a[0]), "r"(a[1]), "r"(a[2]), "r"(a[3]), "r"(b0), "r"(b1));
}

__device__ __forceinline__ void load_chunk(uint32_t stage, int m0, int n0, int k0, int tid) {
    const __half* xa = g_xh + (size_t)m0 * DIM_K + k0;
    const __half* wb = g_wb + (size_t)n0 * DIM_K + k0;
    #pragma unroll
    for (int i = tid; i < 2048; i += 512) {          // A: 256 rows x 8 x 16B
        int r = i >> 3, c = i & 7;
        cp16(stage + swz((uint32_t)(r * 128 + c * 16)), xa + (size_t)r * DIM_K + c * 8);
    }
    #pragma unroll
    for (int i = tid; i < 1024; i += 512) {          // B: 128 rows x 8 x 16B
        int r = i >> 3, c = i & 7;
        cp16(stage + A_BYTES + swz((uint32_t)(r * 128 + c * 16)),
             wb + (size_t)r * DIM_K + c * 8);
    }
}

__global__ void __launch_bounds__(512, 1)
binlin_gemm(const float* __restrict__ bias, float* __restrict__ out) {
    extern __shared__ char smem[];
    const int tid = threadIdx.x, lane = tid & 31, w = tid >> 5;
    const int wm = w >> 2, wn = w & 3;               // 4(m) x 4(n); warp = 64x32
    const int m0 = blockIdx.y * BM, n0 = blockIdx.x * BN;
    const uint32_t sb = smem_u32(smem);

    float acc[4][4][4];
    #pragma unroll
    for (int i = 0; i < 4; ++i)
        #pragma unroll
        for (int j = 0; j < 4; ++j)
            #pragma unroll
            for (int t = 0; t < 4; ++t) acc[i][j][t] = 0.f;

    load_chunk(sb, m0, n0, 0, tid);
    asm volatile("cp.async.commit_group;" ::: "memory");
    load_chunk(sb + STG_BYTES, m0, n0, BK, tid);
    asm volatile("cp.async.commit_group;" ::: "memory");

    const int lrow = lane & 15, lkh = lane >> 4;     // ldmatrix row, k-half
    // Hoisted swizzled row-base offsets (stage-relative); per-step = base + kb.
    uint32_t abase[4], bbase[2];
    #pragma unroll
    for (int mt = 0; mt < 4; ++mt)
        abase[mt] = (uint32_t)((wm * 64 + mt * 16 + lrow) * 128);
    #pragma unroll
    for (int nb = 0; nb < 2; ++nb)
        bbase[nb] = (uint32_t)((wn * 32 + nb * 16 + lrow) * 128);

    for (int c = 0; c < NCH; ++c) {
        __syncthreads();
        if (c + 2 < NCH) {
            load_chunk(sb + ((c + 2) % 3) * STG_BYTES, m0, n0, (c + 2) * BK, tid);
            asm volatile("cp.async.commit_group;" ::: "memory");
            asm volatile("cp.async.wait_group 2;" ::: "memory");
        } else if (c + 1 < NCH) {
            asm volatile("cp.async.wait_group 1;" ::: "memory");
        } else {
            asm volatile("cp.async.wait_group 0;" ::: "memory");
        }
        __syncthreads();
        const uint32_t sa = sb + (c % 3) * STG_BYTES;
        const uint32_t sB = sa + A_BYTES;
        #pragma unroll
        for (int ks = 0; ks < 4; ++ks) {
            const uint32_t kb = (uint32_t)(ks * 32 + lkh * 16);
            uint32_t a[4][4], b[2][4];
            #pragma unroll
            for (int mt = 0; mt < 4; ++mt)
                ldm4(a[mt], sa + swz(abase[mt] + kb));
            #pragma unroll
            for (int nb = 0; nb < 2; ++nb)
                ldm4(b[nb], sB + swz(bbase[nb] + kb));
            #pragma unroll
            for (int mt = 0; mt < 4; ++mt)
                #pragma unroll
                for (int nb = 0; nb < 2; ++nb) {
                    mma16816(acc[mt][nb * 2 + 0], a[mt], b[nb][0], b[nb][2]);
                    mma16816(acc[mt][nb * 2 + 1], a[mt], b[nb][1], b[nb][3]);
                }
        }
    }

    // Epilogue: m = m0 + wm*64 + mt*16 + lane/4 (+8), n = n0 + wn*32 + nt*8 + (lane&3)*2
    float2 bv[4];
    #pragma unroll
    for (int nt = 0; nt < 4; ++nt)
        bv[nt] = *(const float2*)&bias[n0 + wn * 32 + nt * 8 + (lane & 3) * 2];
    #pragma unroll
    for (int mt = 0; mt < 4; ++mt) {
        const int mrow = m0 + wm * 64 + mt * 16 + (lane >> 2);
        #pragma unroll
        for (int nt = 0; nt < 4; ++nt) {
            const int gn = n0 + wn * 32 + nt * 8 + (lane & 3) * 2;
            float2 v0 = make_float2(acc[mt][nt][0] + bv[nt].x, acc[mt][nt][1] + bv[nt].y);
            float2 v1 = make_float2(acc[mt][nt][2] + bv[nt].x, acc[mt][nt][3] + bv[nt].y);
            *(float2*)&out[(size_t)mrow * DIM_N + gn] = v0;
            *(float2*)&out[(size_t)(mrow + 8) * DIM_N + gn] = v1;
        }
    }
}

__global__ void conv_x(const float4* __restrict__ x) {
    const size_t n4 = (size_t)DIM_M * DIM_K / 4;
    uint2* p = (uint2*)g_xh;
    for (size_t i = (size_t)blockIdx.x * blockDim.x + threadIdx.x; i < n4;
         i += (size_t)gridDim.x * blockDim.x) {
        float4 v = x[i];
        __half2 lo = __floats2half2_rn(v.x, v.y);
        __half2 hi = __floats2half2_rn(v.z, v.w);
        uint2 o;
        o.x = *(uint32_t*)&lo;
        o.y = *(uint32_t*)&hi;
        p[i] = o;
    }
}

__global__ void conv_w(const float4* __restrict__ w) {
    const size_t n4 = (size_t)DIM_N * DIM_K / 4;
    ushort4* p = (ushort4*)g_wb;
    for (size_t i = (size_t)blockIdx.x * blockDim.x + threadIdx.x; i < n4;
         i += (size_t)gridDim.x * blockDim.x) {
        float4 v = w[i];
        ushort4 o;
        o.x = (v.x >= 0.f) ? 0x3C00 : 0xBC00;   // +/-1.0 fp16
        o.y = (v.y >= 0.f) ? 0x3C00 : 0xBC00;
        o.z = (v.z >= 0.f) ? 0x3C00 : 0xBC00;
        o.w = (v.w >= 0.f) ? 0x3C00 : 0xBC00;
        p[i] = o;
    }
}

extern "C" void kernel_launch(void* const* d_in, const int* in_sizes, int n_in,
                              void* d_out, int out_size) {
    const float* x = (const float*)d_in[0];
    const float* w = (const float*)d_in[1];
    const float* bias = (const float*)d_in[2];
    float* out = (float*)d_out;
    conv_x<<<2048, 256>>>((const float4*)x);
    conv_w<<<1024, 256>>>((const float4*)w);
    cudaFuncSetAttribute(binlin_gemm, cudaFuncAttributeMaxDynamicSharedMemorySize, SMEM_TOTAL);
    dim3 grid(DIM_N / BN, DIM_M / BM);   // 32 x 32 = 1024 CTAs
    binlin_gemm<<<grid, 512, SMEM_TOTAL>>>(bias, out);
}

// round 14
// speedup vs baseline: 1.0947x; 1.0947x over previous
#include <cuda_runtime.h>
#include <cuda_fp16.h>
#include <cstdint>
#include <cstddef>

// y[8192,4096] = x @ sign(W)^T + bias. fp16 mma.sync GEMM, 128x128x64 tiles,
// 256 threads, 3-stage cp.async pipeline, 2 CTAs/SM, 1 barrier/iteration.
#define DIM_M 8192
#define DIM_N 4096
#define DIM_K 4096
#define BK 64
#define NCH (DIM_K / BK)            // 64
#define STG_BYTES 32768             // A 16K + B 16K
#define SMEM_TOTAL (3 * STG_BYTES)  // 96 KB -> 2 CTAs/SM

__device__ __half g_xh[(size_t)DIM_M * DIM_K];   // 64 MB
__device__ __half g_wb[(size_t)DIM_N * DIM_K];   // 32 MB

__device__ __forceinline__ uint32_t smem_u32(const void* p) {
    uint32_t a;
    asm("{ .reg .u64 t; cvta.to.shared.u64 t, %1; cvt.u32.u64 %0, t; }" : "=r"(a) : "l"(p));
    return a;
}
__device__ __forceinline__ uint32_t swz(uint32_t off) { return off ^ ((off >> 3) & 0x70); }
__device__ __forceinline__ void cp16(uint32_t dst, const void* src) {
    asm volatile("cp.async.cg.shared.global [%0], [%1], 16;" :: "r"(dst), "l"(src));
}
__device__ __forceinline__ void ldm4(uint32_t* r, uint32_t addr) {
    asm volatile("ldmatrix.sync.aligned.m8n8.x4.shared.b16 {%0,%1,%2,%3}, [%4];"
                 : "=r"(r[0]), "=r"(r[1]), "=r"(r[2]), "=r"(r[3]) : "r"(addr));
}
__device__ __forceinline__ void mma16816(float* d, const uint32_t* a,
                                         uint32_t b0, uint32_t b1) {
    asm volatile(
        "mma.sync.aligned.m16n8k16.row.col.f32.f16.f16.f32 "
        "{%0,%1,%2,%3}, {%4,%5,%6,%7}, {%8,%9}, {%0,%1,%2,%3};"
        : "+f"(d[0]), "+f"(d[1]), "+f"(d[2]), "+f"(d[3])
        : "r"(a[0]), "r"(a[1]), "r"(a[2]), "r"(a[3]), "r"(b0), "r"(b1));
}

__device__ __forceinline__ void load_chunk(uint32_t stage, int m0, int n0, int k0, int tid) {
    const __half* xa = g_xh + (size_t)m0 * DIM_K + k0;
    const __half* wb = g_wb + (size_t)n0 * DIM_K + k0;
    #pragma unroll
    for (int i = tid; i < 1024; i += 256) {          // 128 rows x 8 x 16B each
        int r = i >> 3, c = i & 7;
        uint32_t d = swz((uint32_t)(r * 128 + c * 16));
        cp16(stage + d, xa + (size_t)r * DIM_K + c * 8);
        cp16(stage + 16384 + d, wb + (size_t)r * DIM_K + c * 8);
    }
}

__global__ void __launch_bounds__(256, 2)
binlin_gemm(const float* __restrict__ bias, float* __restrict__ out) {
    extern __shared__ char smem[];
    const int tid = threadIdx.x, lane = tid & 31, w = tid >> 5;
    const int wm = w & 3, wn = w >> 2;               // 4(m) x 2(n); warp = 32x64
    const int m0 = blockIdx.y * 128, n0 = blockIdx.x * 128;
    const uint32_t sb = smem_u32(smem);

    float acc[2][8][4];
    #pragma unroll
    for (int i = 0; i < 2; ++i)
        #pragma unroll
        for (int j = 0; j < 8; ++j)
            #pragma unroll
            for (int t = 0; t < 4; ++t) acc[i][j][t] = 0.f;

    load_chunk(sb, m0, n0, 0, tid);
    asm volatile("cp.async.commit_group;" ::: "memory");
    load_chunk(sb + STG_BYTES, m0, n0, BK, tid);
    asm volatile("cp.async.commit_group;" ::: "memory");

    const int lrow = lane & 15, lkh = lane >> 4;
    uint32_t abase[2], bbase[4];
    #pragma unroll
    for (int mt = 0; mt < 2; ++mt)
        abase[mt] = (uint32_t)((wm * 32 + mt * 16 + lrow) * 128);
    #pragma unroll
    for (int nt = 0; nt < 4; ++nt)
        bbase[nt] = (uint32_t)((wn * 64 + nt * 16 + lrow) * 128);

    for (int c = 0; c < NCH; ++c) {
        // stage c complete for THIS thread...
        if (c < NCH - 1) { asm volatile("cp.async.wait_group 1;" ::: "memory"); }
        else            { asm volatile("cp.async.wait_group 0;" ::: "memory"); }
        __syncthreads();   // ...and for all threads; also fences stage (c-1)%3 reads
        if (c + 2 < NCH) {
            load_chunk(sb + ((c + 2) % 3) * STG_BYTES, m0, n0, (c + 2) * BK, tid);
            asm volatile("cp.async.commit_group;" ::: "memory");
        }
        const uint32_t sa = sb + (c % 3) * STG_BYTES;
        const uint32_t sB = sa + 16384;
        #pragma unroll
        for (int ks = 0; ks < 4; ++ks) {
            const uint32_t kb = (uint32_t)(ks * 32 + lkh * 16);
            uint32_t a[2][4], b[4][4];
            #pragma unroll
            for (int mt = 0; mt < 2; ++mt)
                ldm4(a[mt], sa + swz(abase[mt] + kb));
            #pragma unroll
            for (int nt = 0; nt < 4; ++nt)
                ldm4(b[nt], sB + swz(bbase[nt] + kb));
            #pragma unroll
            for (int mt = 0; mt < 2; ++mt)
                #pragma unroll
                for (int nt = 0; nt < 4; ++nt) {
                    mma16816(acc[mt][nt * 2 + 0], a[mt], b[nt][0], b[nt][2]);
                    mma16816(acc[mt][nt * 2 + 1], a[mt], b[nt][1], b[nt][3]);
                }
        }
    }

    // Epilogue: m = m0 + wm*32 + mt*16 + lane/4 (+8), n = n0 + wn*64 + ...
    float2 bv[8];
    #pragma unroll
    for (int j = 0; j < 8; ++j)
        bv[j] = *(const float2*)&bias[n0 + wn * 64 + (j >> 1) * 16 + (j & 1) * 8 + (lane & 3) * 2];
    #pragma unroll
    for (int mt = 0; mt < 2; ++mt) {
        const int mrow = m0 + wm * 32 + mt * 16 + (lane >> 2);
        #pragma unroll
        for (int j = 0; j < 8; ++j) {
            const int gn = n0 + wn * 64 + (j >> 1) * 16 + (j & 1) * 8 + (lane & 3) * 2;
            float2 v0 = make_float2(acc[mt][j][0] + bv[j].x, acc[mt][j][1] + bv[j].y);
            float2 v1 = make_float2(acc[mt][j][2] + bv[j].x, acc[mt][j][3] + bv[j].y);
            *(float2*)&out[(size_t)mrow * DIM_N + gn] = v0;
            *(float2*)&out[(size_t)(mrow + 8) * DIM_N + gn] = v1;
        }
    }
}

// Fused convert: x -> fp16 (rn), W -> sign(W) fp16, one grid-stride kernel.
#define N4X ((size_t)DIM_M * DIM_K / 4)
#define N4W ((size_t)DIM_N * DIM_K / 4)
__global__ void conv_all(const float4* __restrict__ x, const float4* __restrict__ w) {
    uint2* px = (uint2*)g_xh;
    ushort4* pw = (ushort4*)g_wb;
    for (size_t i = (size_t)blockIdx.x * blockDim.x + threadIdx.x; i < N4X + N4W;
         i += (size_t)gridDim.x * blockDim.x) {
        if (i < N4X) {
            float4 v = x[i];
            __half2 lo = __floats2half2_rn(v.x, v.y);
            __half2 hi = __floats2half2_rn(v.z, v.w);
            uint2 o;
            o.x = *(uint32_t*)&lo;
            o.y = *(uint32_t*)&hi;
            px[i] = o;
        } else {
            size_t j = i - N4X;
            float4 v = w[j];
            ushort4 o;
            o.x = (v.x >= 0.f) ? 0x3C00 : 0xBC00;
            o.y = (v.y >= 0.f) ? 0x3C00 : 0xBC00;
            o.z = (v.z >= 0.f) ? 0x3C00 : 0xBC00;
            o.w = (v.w >= 0.f) ? 0x3C00 : 0xBC00;
            pw[j] = o;
        }
    }
}

extern "C" void kernel_launch(void* const* d_in, const int* in_sizes, int n_in,
                              void* d_out, int out_size) {
    const float* x = (const float*)d_in[0];
    const float* w = (const float*)d_in[1];
    const float* bias = (const float*)d_in[2];
    float* out = (float*)d_out;
    conv_all<<<3072, 256>>>((const float4*)x, (const float4*)w);
    cudaFuncSetAttribute(binlin_gemm, cudaFuncAttributeMaxDynamicSharedMemorySize, SMEM_TOTAL);
    dim3 grid(DIM_N / 128, DIM_M / 128);   // 32 x 64 = 2048 CTAs
    binlin_gemm<<<grid, 256, SMEM_TOTAL>>>(bias, out);
}